// round 9
// baseline (speedup 1.0000x reference)
#include <cuda_runtime.h>
#include <math.h>

#define D     768
#define KS    12
#define TT    3
#define BB    32
#define NN    1369
#define HH    8
#define HDIM  96
#define MR    (BB*KS)     // 384 slot rows
#define FR    (BB*NN)     // 43808 feature rows
#define USPLIT 8
#define QK_SCALE 0.03608439182435161f   // 768^-0.5
#define HD_SCALE 0.10206207261596577f   // 96^-0.5

// ---------------- scratch (device globals; no allocations) ----------------
__device__ float g_fn[(size_t)FR*D];      // LN(features), invariant
__device__ float g_sn[MR*D];
__device__ float g_q[MR*D];               // sn @ (Wq Wk^T)
__device__ float g_attn[(size_t)BB*NN*KS];
__device__ float g_mass[MR];
__device__ float g_u_part[(size_t)USPLIT*MR*D];
__device__ float g_u[MR*D];
__device__ float g_upd[MR*D];
__device__ float g_x[MR*D];
__device__ float g_h[MR*D];
__device__ float g_qkv[MR*3*D];
__device__ float g_o[MR*D];
__device__ float g_resid[MR*D];
__device__ float g_mlp[MR*4*D];
__device__ float g_slots[MR*D];
__device__ float g_Wqk[D*D];              // Wq @ Wk^T

__device__ __forceinline__ float gelu_f(float x){
    return 0.5f*x*(1.0f + erff(x*0.7071067811865476f));
}

// ---------------- layernorm (row = 768, 256 threads/row) ----------------
__global__ void ln_kernel(const float* __restrict__ x, const float* __restrict__ x2,
                          const float* __restrict__ g, const float* __restrict__ b,
                          float* __restrict__ out)
{
    int row = blockIdx.x;
    int tid = threadIdx.x;
    const float* xr = x + (size_t)row*D;
    float v[3]; float s=0.f, sq=0.f;
    #pragma unroll
    for (int i=0;i<3;i++){
        int c = tid + i*256;
        float val = xr[c];
        if (x2) val += x2[(size_t)row*D + c];
        v[i]=val; s+=val; sq = fmaf(val,val,sq);
    }
    __shared__ float r0[8], r1[8];
    #pragma unroll
    for (int o=16;o;o>>=1){ s += __shfl_xor_sync(0xffffffffu,s,o); sq += __shfl_xor_sync(0xffffffffu,sq,o); }
    if ((tid&31)==0){ r0[tid>>5]=s; r1[tid>>5]=sq; }
    __syncthreads();
    if (tid==0){
        float S=0.f,SQ=0.f;
        #pragma unroll
        for (int i=0;i<8;i++){ S+=r0[i]; SQ+=r1[i]; }
        float m = S*(1.0f/D);
        float var = SQ*(1.0f/D) - m*m;
        r0[0]=m; r1[0]=rsqrtf(var + 1e-5f);
    }
    __syncthreads();
    float m=r0[0], inv=r1[0];
    #pragma unroll
    for (int i=0;i<3;i++){
        int c = tid + i*256;
        out[(size_t)row*D + c] = (v[i]-m)*inv*g[c] + b[c];
    }
}

// ------ 64x64x16 fp32 GEMM, register-prefetch pipelined (256 thr, 4x4) ------
// C[M,N] = epilogue(A[M,K] @ B[K,N]); TRB: B given as [N,K] (use B^T)
template<bool BIAS,bool GELU_,bool RES,bool TRB>
__global__ void __launch_bounds__(256, 4)
gemm64(const float* __restrict__ A, const float* __restrict__ Bm,
       const float* __restrict__ bias, const float* __restrict__ res,
       float* __restrict__ C, int M, int Kd, int N)
{
    __shared__ __align__(16) float As[16][68];
    __shared__ __align__(16) float Bs[16][68];
    int tid = threadIdx.x;
    int tx = tid & 15, ty = tid >> 4;
    int bm = blockIdx.y, bn = blockIdx.x;
    int ar = tid >> 2, ac = (tid & 3) << 2;
    float acc[4][4];
    #pragma unroll
    for (int i=0;i<4;i++){ acc[i][0]=0.f; acc[i][1]=0.f; acc[i][2]=0.f; acc[i][3]=0.f; }
    const float* Ap = A + (size_t)(bm*64 + ar)*Kd + ac;
    const float* Bp;
    if (TRB) Bp = Bm + (size_t)(bn*64 + ar)*Kd + ac;
    else     Bp = Bm + (size_t)(tid>>4)*N + bn*64 + ((tid&15)<<2);

    float4 av = *(const float4*)Ap; Ap += 16;
    float4 bv;
    if (TRB){ bv = *(const float4*)Bp; Bp += 16; }
    else    { bv = *(const float4*)Bp; Bp += (size_t)16*N; }

    for (int kk=0; kk<Kd; kk+=16){
        As[ac+0][ar]=av.x; As[ac+1][ar]=av.y; As[ac+2][ar]=av.z; As[ac+3][ar]=av.w;
        if (TRB){
            Bs[ac+0][ar]=bv.x; Bs[ac+1][ar]=bv.y; Bs[ac+2][ar]=bv.z; Bs[ac+3][ar]=bv.w;
        } else {
            *(float4*)&Bs[tid>>4][(tid&15)<<2] = bv;
        }
        __syncthreads();
        if (kk + 16 < Kd){
            av = *(const float4*)Ap; Ap += 16;
            if (TRB){ bv = *(const float4*)Bp; Bp += 16; }
            else    { bv = *(const float4*)Bp; Bp += (size_t)16*N; }
        }
        #pragma unroll
        for (int k=0;k<16;k++){
            float4 a4 = *(const float4*)&As[k][ty<<2];
            float4 b4 = *(const float4*)&Bs[k][tx<<2];
            float avr[4]={a4.x,a4.y,a4.z,a4.w};
            float bvr[4]={b4.x,b4.y,b4.z,b4.w};
            #pragma unroll
            for (int i=0;i<4;i++)
                #pragma unroll
                for (int j=0;j<4;j++)
                    acc[i][j] = fmaf(avr[i], bvr[j], acc[i][j]);
        }
        __syncthreads();
    }
    int row0 = bm*64 + (ty<<2), col0 = bn*64 + (tx<<2);
    #pragma unroll
    for (int i=0;i<4;i++){
        #pragma unroll
        for (int j=0;j<4;j++){
            float v = acc[i][j];
            if (BIAS) v += bias[col0+j];
            if (GELU_) v = gelu_f(v);
            if (RES) v += res[(size_t)(row0+i)*N + col0+j];
            C[(size_t)(row0+i)*N + col0+j] = v;
        }
    }
}

// -- 32x64x16 fp32 GEMM, register-prefetch pipelined (128 thr, 4x4; 144-blk grid) --
template<bool BIAS,bool GELU_,bool RES>
__global__ void __launch_bounds__(128, 8)
gemm32(const float* __restrict__ A, const float* __restrict__ Bm,
       const float* __restrict__ bias, const float* __restrict__ res,
       float* __restrict__ C, int M, int Kd, int N)
{
    __shared__ __align__(16) float As[16][36];
    __shared__ __align__(16) float Bs[16][68];
    int tid = threadIdx.x;                     // 128 threads
    int tx = tid & 15, ty = tid >> 4;          // tx: 16 col groups, ty: 8 row groups
    int bm = blockIdx.y, bn = blockIdx.x;
    int ar = tid >> 2, ac = (tid & 3) << 2;    // A: 32 rows x 16k -> 128 float4
    float acc[4][4];
    #pragma unroll
    for (int i=0;i<4;i++){ acc[i][0]=0.f; acc[i][1]=0.f; acc[i][2]=0.f; acc[i][3]=0.f; }
    const float* Ap = A + (size_t)(bm*32 + ar)*Kd + ac;
    int bk0 = tid >> 4, bc0 = (tid & 15) << 2;          // k 0..7
    const float* Bp0 = Bm + (size_t)bk0*N + bn*64 + bc0;
    const float* Bp1 = Bp0 + (size_t)8*N;               // k 8..15

    float4 av  = *(const float4*)Ap;  Ap  += 16;
    float4 bv0 = *(const float4*)Bp0; Bp0 += (size_t)16*N;
    float4 bv1 = *(const float4*)Bp1; Bp1 += (size_t)16*N;

    for (int kk=0; kk<Kd; kk+=16){
        As[ac+0][ar]=av.x; As[ac+1][ar]=av.y; As[ac+2][ar]=av.z; As[ac+3][ar]=av.w;
        *(float4*)&Bs[bk0  ][bc0] = bv0;
        *(float4*)&Bs[bk0+8][bc0] = bv1;
        __syncthreads();
        if (kk + 16 < Kd){
            av  = *(const float4*)Ap;  Ap  += 16;
            bv0 = *(const float4*)Bp0; Bp0 += (size_t)16*N;
            bv1 = *(const float4*)Bp1; Bp1 += (size_t)16*N;
        }
        #pragma unroll
        for (int k=0;k<16;k++){
            float4 a4 = *(const float4*)&As[k][ty<<2];
            float4 b4 = *(const float4*)&Bs[k][tx<<2];
            float avr[4]={a4.x,a4.y,a4.z,a4.w};
            float bvr[4]={b4.x,b4.y,b4.z,b4.w};
            #pragma unroll
            for (int i=0;i<4;i++)
                #pragma unroll
                for (int j=0;j<4;j++)
                    acc[i][j] = fmaf(avr[i], bvr[j], acc[i][j]);
        }
        __syncthreads();
    }
    int row0 = bm*32 + (ty<<2), col0 = bn*64 + (tx<<2);
    #pragma unroll
    for (int i=0;i<4;i++){
        #pragma unroll
        for (int j=0;j<4;j++){
            float v = acc[i][j];
            if (BIAS) v += bias[col0+j];
            if (GELU_) v = gelu_f(v);
            if (RES) v += res[(size_t)(row0+i)*N + col0+j];
            C[(size_t)(row0+i)*N + col0+j] = v;
        }
    }
}

// ---------------- fused logits + competitive softmax ----------------
// logits[b,k,n] = (g_q[b,k,:] . g_fn[b,n,:]) * QK_SCALE ; softmax over k per (b,n)
__global__ void attn_softmax_kernel(float* __restrict__ attn_out)
{
    __shared__ __align__(16) float qs[KS*D];   // 36 KB
    int b = blockIdx.y;
    int n0 = blockIdx.x * 32;
    int tid = threadIdx.x;
    const float* qb = g_q + (size_t)b*KS*D;
    for (int i=tid; i<KS*D/4; i+=256)
        ((float4*)qs)[i] = ((const float4*)qb)[i];
    __syncthreads();
    int warp = tid>>5, lane = tid&31;
    for (int nw=0; nw<4; nw++){
        int n = n0 + warp*4 + nw;
        if (n >= NN) continue;
        const float* f = g_fn + ((size_t)b*NN + n)*D;
        float acc[KS];
        #pragma unroll
        for (int k=0;k<KS;k++) acc[k]=0.f;
        for (int d0=0; d0<D; d0+=32){
            float fv = f[d0+lane];
            #pragma unroll
            for (int k=0;k<KS;k++) acc[k] = fmaf(fv, qs[k*D + d0 + lane], acc[k]);
        }
        #pragma unroll
        for (int k=0;k<KS;k++){
            #pragma unroll
            for (int o=16;o;o>>=1) acc[k] += __shfl_xor_sync(0xffffffffu, acc[k], o);
        }
        float mx = -1e30f;
        #pragma unroll
        for (int k=0;k<KS;k++){ acc[k]*=QK_SCALE; mx = fmaxf(mx, acc[k]); }
        float s=0.f;
        #pragma unroll
        for (int k=0;k<KS;k++){ acc[k]=expf(acc[k]-mx); s+=acc[k]; }
        float inv = 1.0f/s;
        if (lane < KS){
            float val=0.f;
            #pragma unroll
            for (int k=0;k<KS;k++) if (lane==k) val = acc[k];
            attn_out[((size_t)b*NN + n)*KS + lane] = val*inv;
        }
    }
}

// ---------------- mass[b,k] = sum_n attn[b,n,k] (deterministic) ----------------
__global__ void mass_kernel(const float* __restrict__ attn)
{
    __shared__ float part[256][KS];
    int b = blockIdx.x, tid = threadIdx.x;
    float acc[KS];
    #pragma unroll
    for (int k=0;k<KS;k++) acc[k]=0.f;
    for (int n=tid; n<NN; n+=256){
        const float* r = attn + ((size_t)b*NN + n)*KS;
        #pragma unroll
        for (int k=0;k<KS;k++) acc[k] += r[k];
    }
    #pragma unroll
    for (int k=0;k<KS;k++) part[tid][k] = acc[k];
    __syncthreads();
    if (tid < KS){
        float s = 0.f;
        for (int i=0;i<256;i++) s += part[i][tid];
        g_mass[b*KS + tid] = s;
    }
}

// ---------------- u_part[s,b,k,d] = sum_{n in split s} attn[b,n,k]*fn[b,n,d] ----
__global__ void u_part_kernel(const float* __restrict__ attn)
{
    __shared__ float as[64*KS];
    int b = blockIdx.z;
    int sp = blockIdx.y;
    int d = blockIdx.x*256 + threadIdx.x;
    const int nchunk = (NN + USPLIT - 1)/USPLIT;   // 172
    int ns = sp * nchunk;
    int ne = min(ns + nchunk, NN);
    float acc[KS];
    #pragma unroll
    for (int k=0;k<KS;k++) acc[k]=0.f;
    for (int nb=ns; nb<ne; nb+=64){
        int cnt = min(64, ne-nb);
        __syncthreads();
        for (int i=threadIdx.x; i<cnt*KS; i+=256)
            as[i] = attn[((size_t)b*NN + nb)*KS + i];
        __syncthreads();
        for (int j=0;j<cnt;j++){
            float fv = g_fn[((size_t)b*NN + nb + j)*D + d];
            #pragma unroll
            for (int k=0;k<KS;k++) acc[k] = fmaf(fv, as[j*KS+k], acc[k]);
        }
    }
    #pragma unroll
    for (int k=0;k<KS;k++)
        g_u_part[((size_t)sp*MR + b*KS + k)*D + d] = acc[k];
}

// ---------------- u = (sum of partials) / max(mass, eps), fixed order --------
__global__ void u_combine_kernel(){
    int i = blockIdx.x*256 + threadIdx.x;
    if (i >= MR*D) return;
    float s = 0.f;
    #pragma unroll
    for (int p=0;p<USPLIT;p++) s += g_u_part[(size_t)p*MR*D + i];
    g_u[i] = s / fmaxf(g_mass[i/D], 1e-8f);
}

// ---------------- tiny 12-token 8-head transformer attention ----------------
__global__ void block_attn_kernel()
{
    int b = blockIdx.x / HH, h = blockIdx.x % HH;
    __shared__ float qs[KS*HDIM], ks2[KS*HDIM], vs[KS*HDIM], sc[KS*KS];
    int tid = threadIdx.x;  // 128
    for (int i=tid;i<KS*HDIM;i+=128){
        int s=i/HDIM, c=i%HDIM;
        const float* r = g_qkv + (size_t)(b*KS+s)*(3*D) + h*HDIM + c;
        qs[i]=r[0]; ks2[i]=r[D]; vs[i]=r[2*D];
    }
    __syncthreads();
    for (int t=tid;t<KS*KS;t+=128){
        int i=t/KS, j=t%KS;
        float sum=0.f;
        #pragma unroll
        for (int c=0;c<HDIM;c++) sum = fmaf(qs[i*HDIM+c], ks2[j*HDIM+c], sum);
        sc[t] = sum * HD_SCALE;
    }
    __syncthreads();
    if (tid < KS){
        float mx=-1e30f;
        #pragma unroll
        for (int j=0;j<KS;j++) mx=fmaxf(mx, sc[tid*KS+j]);
        float s=0.f;
        #pragma unroll
        for (int j=0;j<KS;j++){ float e=expf(sc[tid*KS+j]-mx); sc[tid*KS+j]=e; s+=e; }
        float inv=1.0f/s;
        #pragma unroll
        for (int j=0;j<KS;j++) sc[tid*KS+j]*=inv;
    }
    __syncthreads();
    for (int i=tid;i<KS*HDIM;i+=128){
        int s=i/HDIM, c=i%HDIM;
        float o=0.f;
        #pragma unroll
        for (int j=0;j<KS;j++) o = fmaf(sc[s*KS+j], vs[j*HDIM+c], o);
        g_o[(size_t)(b*KS+s)*D + h*HDIM + c] = o;
    }
}

__global__ void copyk(const float* __restrict__ s, float* __restrict__ d, int n){
    int i = blockIdx.x*blockDim.x + threadIdx.x;
    if (i < n) d[i] = s[i];
}

// ---------------- host orchestration ----------------
extern "C" void kernel_launch(void* const* d_in, const int* in_sizes, int n_in,
                              void* d_out, int out_size)
{
    (void)in_sizes; (void)n_in;
    const float* features  = (const float*)d_in[0];
    const float* slots_init= (const float*)d_in[1];
    const float* nf_g=(const float*)d_in[2];  const float* nf_b=(const float*)d_in[3];
    const float* ns_g=(const float*)d_in[4];  const float* ns_b=(const float*)d_in[5];
    const float* Wq =(const float*)d_in[6];   const float* Wk =(const float*)d_in[7];
    const float* Wv =(const float*)d_in[8];
    const float* mg =(const float*)d_in[9];   const float* mb =(const float*)d_in[10];
    const float* mW1=(const float*)d_in[11];  const float* mb1=(const float*)d_in[12];
    const float* mW2=(const float*)d_in[13];  const float* mb2=(const float*)d_in[14];
    const float* b_ln1g=(const float*)d_in[15]; const float* b_ln1b=(const float*)d_in[16];
    const float* b_Wqkv=(const float*)d_in[17]; const float* b_bqkv=(const float*)d_in[18];
    const float* b_Wo=(const float*)d_in[19];   const float* b_bo=(const float*)d_in[20];
    const float* b_ln2g=(const float*)d_in[21]; const float* b_ln2b=(const float*)d_in[22];
    const float* b_W1=(const float*)d_in[23];   const float* b_b1=(const float*)d_in[24];
    const float* b_W2=(const float*)d_in[25];   const float* b_b2=(const float*)d_in[26];

    float *pFn,*pSn,*pQ,*pAttn,*pU,*pUpd,*pX,*pH,*pQkv,*pO,*pResid,*pMlp,*pSlots,*pWqk;
    cudaGetSymbolAddress((void**)&pFn, g_fn);
    cudaGetSymbolAddress((void**)&pSn, g_sn);
    cudaGetSymbolAddress((void**)&pQ, g_q);
    cudaGetSymbolAddress((void**)&pAttn, g_attn);
    cudaGetSymbolAddress((void**)&pU, g_u);
    cudaGetSymbolAddress((void**)&pUpd, g_upd);
    cudaGetSymbolAddress((void**)&pX, g_x);
    cudaGetSymbolAddress((void**)&pH, g_h);
    cudaGetSymbolAddress((void**)&pQkv, g_qkv);
    cudaGetSymbolAddress((void**)&pO, g_o);
    cudaGetSymbolAddress((void**)&pResid, g_resid);
    cudaGetSymbolAddress((void**)&pMlp, g_mlp);
    cudaGetSymbolAddress((void**)&pSlots, g_slots);
    cudaGetSymbolAddress((void**)&pWqk, g_Wqk);

    float* out = (float*)d_out;
    float* mask_dst;
    bool write_slots = true;
    if (out_size == BB*NN*KS){ mask_dst = out; write_slots = false; }
    else if (out_size >= MR*D + BB*NN*KS){ mask_dst = out + MR*D; }
    else { mask_dst = pAttn; }   // slots-only output

    // ---- invariant precompute ----
    copyk<<<(MR*D+255)/256,256>>>(slots_init, pSlots, MR*D);
    ln_kernel<<<FR,256>>>(features, nullptr, nf_g, nf_b, pFn);
    gemm64<false,false,false,true><<<dim3(D/64,D/64),256>>>(Wq, Wk, nullptr, nullptr, pWqk, D, D, D);

    const int NB = (NN + 31)/32;  // 43
    for (int t=0;t<TT;t++){
        const float* ln1g = b_ln1g + t*D;          const float* ln1b = b_ln1b + t*D;
        const float* Wqkv_t = b_Wqkv + (size_t)t*D*3*D;  const float* bqkv_t = b_bqkv + t*3*D;
        const float* Wo_t = b_Wo + (size_t)t*D*D;  const float* bo_t = b_bo + t*D;
        const float* ln2g = b_ln2g + t*D;          const float* ln2b = b_ln2b + t*D;
        const float* W1_t = b_W1 + (size_t)t*D*4*D; const float* b1_t = b_b1 + t*4*D;
        const float* W2_t = b_W2 + (size_t)t*4*D*D; const float* b2_t = b_b2 + t*D;

        // slot->feature attention (restructured: q = sn @ Wqk, logits = q.fn^T)
        ln_kernel<<<MR,256>>>(pSlots, nullptr, ns_g, ns_b, pSn);
        gemm32<false,false,false><<<dim3(D/64,MR/32),128>>>(pSn, pWqk, nullptr, nullptr, pQ, MR, D, D);
        attn_softmax_kernel<<<dim3(NB,BB),256>>>(pAttn);
        mass_kernel<<<BB,256>>>(pAttn);
        u_part_kernel<<<dim3(3,USPLIT,BB),256>>>(pAttn);
        u_combine_kernel<<<(MR*D+255)/256,256>>>();
        gemm32<false,false,false><<<dim3(D/64,MR/32),128>>>(pU, Wv, nullptr, nullptr, pUpd, MR, D, D);

        // transformer block on sn
        ln_kernel<<<MR,256>>>(pSn, nullptr, ln1g, ln1b, pH);
        gemm64<true,false,false,false><<<dim3(3*D/64,MR/64),256>>>(pH, Wqkv_t, bqkv_t, nullptr, pQkv, MR, D, 3*D);
        block_attn_kernel<<<BB*HH,128>>>();
        gemm32<true,false,true><<<dim3(D/64,MR/32),128>>>(pO, Wo_t, bo_t, pSn, pX, MR, D, D);
        ln_kernel<<<MR,256>>>(pX, nullptr, ln2g, ln2b, pH);
        gemm64<true,true,false,false><<<dim3(4*D/64,MR/64),256>>>(pH, W1_t, b1_t, nullptr, pMlp, MR, D, 4*D);
        gemm32<true,false,true><<<dim3(D/64,MR/32),128>>>(pMlp, W2_t, b2_t, pX, pResid, MR, 4*D, D);

        // mixer MLP + slot update
        ln_kernel<<<MR,256>>>(pUpd, pResid, mg, mb, pH);
        gemm64<true,true,false,false><<<dim3(4*D/64,MR/64),256>>>(pH, mW1, mb1, nullptr, pMlp, MR, D, 4*D);
        gemm32<true,false,true><<<dim3(D/64,MR/32),128>>>(pMlp, mW2, mb2, pSlots, pSlots, MR, 4*D, D);
    }

    // final masks from updated slots
    ln_kernel<<<MR,256>>>(pSlots, nullptr, ns_g, ns_b, pSn);
    gemm32<false,false,false><<<dim3(D/64,MR/32),128>>>(pSn, pWqk, nullptr, nullptr, pQ, MR, D, D);
    attn_softmax_kernel<<<dim3(NB,BB),256>>>(mask_dst);
    if (write_slots)
        copyk<<<(MR*D+255)/256,256>>>(pSlots, out, MR*D);
}

// round 12
// speedup vs baseline: 1.6354x; 1.6354x over previous
#include <cuda_runtime.h>
#include <math.h>
#include <stdint.h>

#define D     768
#define KS    12
#define TT    3
#define BB    32
#define NN    1369
#define HH    8
#define HDIM  96
#define MR    (BB*KS)     // 384 slot rows
#define FR    (BB*NN)     // 43808 feature rows
#define USPLIT 8
#define QK_SCALE 0.03608439182435161f   // 768^-0.5
#define HD_SCALE 0.10206207261596577f   // 96^-0.5

// ---------------- scratch (device globals; no allocations) ----------------
__device__ float g_fn[(size_t)FR*D];      // LN(features), invariant
__device__ float g_sn[MR*D];
__device__ float g_q[MR*D];               // sn @ (Wq Wk^T)
__device__ float g_attn[(size_t)BB*NN*KS];
__device__ float g_mass[MR];
__device__ float g_u_part[(size_t)USPLIT*MR*D];
__device__ float g_u[MR*D];
__device__ float g_upd[MR*D];
__device__ float g_x[MR*D];
__device__ float g_h[MR*D];
__device__ float g_qkv[MR*3*D];
__device__ float g_o[MR*D];
__device__ float g_resid[MR*D];
__device__ float g_mlp[MR*4*D];
__device__ float g_slots[MR*D];
__device__ float g_Wqk[D*D];              // Wq @ Wk^T

__device__ __forceinline__ float gelu_f(float x){
    return 0.5f*x*(1.0f + erff(x*0.7071067811865476f));
}

__device__ __forceinline__ float tf32r(float x){
    uint32_t u; asm("cvt.rna.tf32.f32 %0, %1;" : "=r"(u) : "f"(x));
    return __uint_as_float(u);
}

__device__ __forceinline__ void mma_tf32(float* d, const uint32_t* a, uint32_t b0, uint32_t b1){
    asm volatile("mma.sync.aligned.m16n8k8.row.col.f32.tf32.tf32.f32 "
        "{%0,%1,%2,%3}, {%4,%5,%6,%7}, {%8,%9}, {%0,%1,%2,%3};"
        : "+f"(d[0]), "+f"(d[1]), "+f"(d[2]), "+f"(d[3])
        : "r"(a[0]), "r"(a[1]), "r"(a[2]), "r"(a[3]), "r"(b0), "r"(b1));
}

// ---------------- layernorm (row = 768, 256 threads/row) ----------------
__global__ void ln_kernel(const float* __restrict__ x, const float* __restrict__ x2,
                          const float* __restrict__ g, const float* __restrict__ b,
                          float* __restrict__ out)
{
    int row = blockIdx.x;
    int tid = threadIdx.x;
    const float* xr = x + (size_t)row*D;
    float v[3]; float s=0.f, sq=0.f;
    #pragma unroll
    for (int i=0;i<3;i++){
        int c = tid + i*256;
        float val = xr[c];
        if (x2) val += x2[(size_t)row*D + c];
        v[i]=val; s+=val; sq = fmaf(val,val,sq);
    }
    __shared__ float r0[8], r1[8];
    #pragma unroll
    for (int o=16;o;o>>=1){ s += __shfl_xor_sync(0xffffffffu,s,o); sq += __shfl_xor_sync(0xffffffffu,sq,o); }
    if ((tid&31)==0){ r0[tid>>5]=s; r1[tid>>5]=sq; }
    __syncthreads();
    if (tid==0){
        float S=0.f,SQ=0.f;
        #pragma unroll
        for (int i=0;i<8;i++){ S+=r0[i]; SQ+=r1[i]; }
        float m = S*(1.0f/D);
        float var = SQ*(1.0f/D) - m*m;
        r0[0]=m; r1[0]=rsqrtf(var + 1e-5f);
    }
    __syncthreads();
    float m=r0[0], inv=r1[0];
    #pragma unroll
    for (int i=0;i<3;i++){
        int c = tid + i*256;
        out[(size_t)row*D + c] = (v[i]-m)*inv*g[c] + b[c];
    }
}

// ---------------- tf32 tensor-core GEMM ----------------
// Block tile: BM x 64, K-chunk 32. 128 threads = 4 warps, layout (BM/32) x WC.
// Warp tile: 32 x (64/WC).  C = epilogue(A[M,K] @ B[K,N]); TRB: B given [N,K].
template<int BM, int WC, bool BIAS, bool GELU_, bool RES, bool TRB>
__global__ void __launch_bounds__(128)
gemmT(const float* __restrict__ A, const float* __restrict__ Bm,
      const float* __restrict__ bias, const float* __restrict__ res,
      float* __restrict__ C, int M, int Kd, int N)
{
    constexpr int SA = BM + 8;      // As stride (words): %32==8 -> conflict-free frag LDS
    constexpr int NT = 8/WC;        // n-tiles (8 cols each) per warp
    constexpr int NA = BM/16;       // A float4 loads per thread
    __shared__ float As[32*SA];
    __shared__ float Bs[32*72];

    int tid = threadIdx.x;
    int wid = tid>>5, lane = tid&31;
    int grp = lane>>2, tig = lane&3;
    int wrow = wid / WC, wcol = wid % WC;
    int bm = blockIdx.y, bn = blockIdx.x;

    float acc[2][NT][4];
    #pragma unroll
    for (int i=0;i<2;i++)
        #pragma unroll
        for (int j=0;j<NT;j++){ acc[i][j][0]=0.f; acc[i][j][1]=0.f; acc[i][j][2]=0.f; acc[i][j][3]=0.f; }

    // global loaders
    int arow = tid>>3, aq = tid&7;
    const float* Ap = A + (size_t)(bm*BM + arow)*Kd + aq*4;
    int bkrow = tid>>4, bq = tid&15;
    int brow = tid>>3, bq2 = tid&7;
    const float* Bp;
    if (TRB) Bp = Bm + (size_t)(bn*64 + brow)*Kd + bq2*4;
    else     Bp = Bm + (size_t)bkrow*N + bn*64 + bq*4;

    float4 pa[NA], pb[4];
    #pragma unroll
    for (int i=0;i<NA;i++) pa[i] = *(const float4*)(Ap + (size_t)(16*i)*Kd);
    if (TRB){
        #pragma unroll
        for (int i=0;i<4;i++) pb[i] = *(const float4*)(Bp + (size_t)(16*i)*Kd);
    } else {
        #pragma unroll
        for (int i=0;i<4;i++) pb[i] = *(const float4*)(Bp + (size_t)(8*i)*N);
    }
    Ap += 32;
    if (TRB) Bp += 32; else Bp += (size_t)32*N;

    for (int kk=0; kk<Kd; kk+=32){
        // ---- store to smem with tf32 rounding + swizzle ----
        #pragma unroll
        for (int i=0;i<NA;i++){
            int row = arow + 16*i;
            float v[4] = {pa[i].x, pa[i].y, pa[i].z, pa[i].w};
            #pragma unroll
            for (int j=0;j<4;j++){
                int k = aq*4 + j;
                As[k*SA + (row ^ ((((k>>2)&7))<<2))] = tf32r(v[j]);
            }
        }
        if (TRB){
            #pragma unroll
            for (int i=0;i<4;i++){
                int row = brow + 16*i;   // n index
                float v[4] = {pb[i].x, pb[i].y, pb[i].z, pb[i].w};
                #pragma unroll
                for (int j=0;j<4;j++){
                    int k = bq2*4 + j;
                    Bs[k*72 + (row ^ ((((k>>2)&7))<<2))] = tf32r(v[j]);
                }
            }
        } else {
            #pragma unroll
            for (int i=0;i<4;i++){
                int kr = bkrow + 8*i;
                float4 cv;
                cv.x = tf32r(pb[i].x); cv.y = tf32r(pb[i].y);
                cv.z = tf32r(pb[i].z); cv.w = tf32r(pb[i].w);
                int cb = (bq*4) ^ ((((kr>>2)&7))<<2);
                *(float4*)&Bs[kr*72 + cb] = cv;
            }
        }
        __syncthreads();
        // ---- prefetch next chunk ----
        if (kk + 32 < Kd){
            #pragma unroll
            for (int i=0;i<NA;i++) pa[i] = *(const float4*)(Ap + (size_t)(16*i)*Kd);
            if (TRB){
                #pragma unroll
                for (int i=0;i<4;i++) pb[i] = *(const float4*)(Bp + (size_t)(16*i)*Kd);
                Bp += 32;
            } else {
                #pragma unroll
                for (int i=0;i<4;i++) pb[i] = *(const float4*)(Bp + (size_t)(8*i)*N);
                Bp += (size_t)32*N;
            }
            Ap += 32;
        }
        // ---- compute ----
        #pragma unroll
        for (int ks=0; ks<4; ks++){
            int k0 = ks*8;
            int kA = k0 + tig, kB = k0 + tig + 4;
            int c1 = (((kA>>2)&7))<<2;   // constant per instruction (tig<4)
            int c2 = (((kB>>2)&7))<<2;
            uint32_t af[2][4];
            #pragma unroll
            for (int mt=0;mt<2;mt++){
                int m0 = wrow*32 + mt*16 + grp;
                af[mt][0] = __float_as_uint(As[kA*SA + ( m0      ^ c1)]);
                af[mt][1] = __float_as_uint(As[kA*SA + ((m0+8)   ^ c1)]);
                af[mt][2] = __float_as_uint(As[kB*SA + ( m0      ^ c2)]);
                af[mt][3] = __float_as_uint(As[kB*SA + ((m0+8)   ^ c2)]);
            }
            #pragma unroll
            for (int nt=0;nt<NT;nt++){
                int n0 = wcol*(NT*8) + nt*8 + grp;
                uint32_t b0 = __float_as_uint(Bs[kA*72 + (n0 ^ c1)]);
                uint32_t b1 = __float_as_uint(Bs[kB*72 + (n0 ^ c2)]);
                #pragma unroll
                for (int mt=0;mt<2;mt++)
                    mma_tf32(acc[mt][nt], af[mt], b0, b1);
            }
        }
        __syncthreads();
    }

    // ---- epilogue ----
    #pragma unroll
    for (int mt=0;mt<2;mt++){
        #pragma unroll
        for (int nt=0;nt<NT;nt++){
            int row0 = bm*BM + wrow*32 + mt*16 + grp;
            int col0 = bn*64 + wcol*(NT*8) + nt*8 + tig*2;
            #pragma unroll
            for (int h=0;h<2;h++){
                int r = row0 + 8*h;
                float vx = acc[mt][nt][2*h];
                float vy = acc[mt][nt][2*h+1];
                if (BIAS){ vx += bias[col0]; vy += bias[col0+1]; }
                if (GELU_){ vx = gelu_f(vx); vy = gelu_f(vy); }
                if (RES){ vx += res[(size_t)r*N + col0]; vy += res[(size_t)r*N + col0+1]; }
                float2 v2; v2.x = vx; v2.y = vy;
                *(float2*)&C[(size_t)r*N + col0] = v2;
            }
        }
    }
}

// ---------------- fused logits + competitive softmax ----------------
__global__ void attn_softmax_kernel(float* __restrict__ attn_out)
{
    __shared__ __align__(16) float qs[KS*D];   // 36 KB
    int b = blockIdx.y;
    int n0 = blockIdx.x * 32;
    int tid = threadIdx.x;
    const float* qb = g_q + (size_t)b*KS*D;
    for (int i=tid; i<KS*D/4; i+=256)
        ((float4*)qs)[i] = ((const float4*)qb)[i];
    __syncthreads();
    int warp = tid>>5, lane = tid&31;
    for (int nw=0; nw<4; nw++){
        int n = n0 + warp*4 + nw;
        if (n >= NN) continue;
        const float* f = g_fn + ((size_t)b*NN + n)*D;
        float acc[KS];
        #pragma unroll
        for (int k=0;k<KS;k++) acc[k]=0.f;
        for (int d0=0; d0<D; d0+=32){
            float fv = f[d0+lane];
            #pragma unroll
            for (int k=0;k<KS;k++) acc[k] = fmaf(fv, qs[k*D + d0 + lane], acc[k]);
        }
        #pragma unroll
        for (int k=0;k<KS;k++){
            #pragma unroll
            for (int o=16;o;o>>=1) acc[k] += __shfl_xor_sync(0xffffffffu, acc[k], o);
        }
        float mx = -1e30f;
        #pragma unroll
        for (int k=0;k<KS;k++){ acc[k]*=QK_SCALE; mx = fmaxf(mx, acc[k]); }
        float s=0.f;
        #pragma unroll
        for (int k=0;k<KS;k++){ acc[k]=expf(acc[k]-mx); s+=acc[k]; }
        float inv = 1.0f/s;
        if (lane < KS){
            float val=0.f;
            #pragma unroll
            for (int k=0;k<KS;k++) if (lane==k) val = acc[k];
            attn_out[((size_t)b*NN + n)*KS + lane] = val*inv;
        }
    }
}

// ---------------- mass[b,k] = sum_n attn[b,n,k] (deterministic) ----------------
__global__ void mass_kernel(const float* __restrict__ attn)
{
    __shared__ float part[256][KS];
    int b = blockIdx.x, tid = threadIdx.x;
    float acc[KS];
    #pragma unroll
    for (int k=0;k<KS;k++) acc[k]=0.f;
    for (int n=tid; n<NN; n+=256){
        const float* r = attn + ((size_t)b*NN + n)*KS;
        #pragma unroll
        for (int k=0;k<KS;k++) acc[k] += r[k];
    }
    #pragma unroll
    for (int k=0;k<KS;k++) part[tid][k] = acc[k];
    __syncthreads();
    if (tid < KS){
        float s = 0.f;
        for (int i=0;i<256;i++) s += part[i][tid];
        g_mass[b*KS + tid] = s;
    }
}

// ---------------- u_part[s,b,k,d] = sum_{n in split s} attn[b,n,k]*fn[b,n,d] ----
__global__ void u_part_kernel(const float* __restrict__ attn)
{
    __shared__ float as[64*KS];
    int b = blockIdx.z;
    int sp = blockIdx.y;
    int d = blockIdx.x*256 + threadIdx.x;
    const int nchunk = (NN + USPLIT - 1)/USPLIT;   // 172
    int ns = sp * nchunk;
    int ne = min(ns + nchunk, NN);
    float acc[KS];
    #pragma unroll
    for (int k=0;k<KS;k++) acc[k]=0.f;
    for (int nb=ns; nb<ne; nb+=64){
        int cnt = min(64, ne-nb);
        __syncthreads();
        for (int i=threadIdx.x; i<cnt*KS; i+=256)
            as[i] = attn[((size_t)b*NN + nb)*KS + i];
        __syncthreads();
        for (int j=0;j<cnt;j++){
            float fv = g_fn[((size_t)b*NN + nb + j)*D + d];
            #pragma unroll
            for (int k=0;k<KS;k++) acc[k] = fmaf(fv, as[j*KS+k], acc[k]);
        }
    }
    #pragma unroll
    for (int k=0;k<KS;k++)
        g_u_part[((size_t)sp*MR + b*KS + k)*D + d] = acc[k];
}

// ---------------- u = (sum of partials) / max(mass, eps), fixed order --------
__global__ void u_combine_kernel(){
    int i = blockIdx.x*256 + threadIdx.x;
    if (i >= MR*D) return;
    float s = 0.f;
    #pragma unroll
    for (int p=0;p<USPLIT;p++) s += g_u_part[(size_t)p*MR*D + i];
    g_u[i] = s / fmaxf(g_mass[i/D], 1e-8f);
}

// ---------------- tiny 12-token 8-head transformer attention ----------------
__global__ void block_attn_kernel()
{
    int b = blockIdx.x / HH, h = blockIdx.x % HH;
    __shared__ float qs[KS*HDIM], ks2[KS*HDIM], vs[KS*HDIM], sc[KS*KS];
    int tid = threadIdx.x;  // 128
    for (int i=tid;i<KS*HDIM;i+=128){
        int s=i/HDIM, c=i%HDIM;
        const float* r = g_qkv + (size_t)(b*KS+s)*(3*D) + h*HDIM + c;
        qs[i]=r[0]; ks2[i]=r[D]; vs[i]=r[2*D];
    }
    __syncthreads();
    for (int t=tid;t<KS*KS;t+=128){
        int i=t/KS, j=t%KS;
        float sum=0.f;
        #pragma unroll
        for (int c=0;c<HDIM;c++) sum = fmaf(qs[i*HDIM+c], ks2[j*HDIM+c], sum);
        sc[t] = sum * HD_SCALE;
    }
    __syncthreads();
    if (tid < KS){
        float mx=-1e30f;
        #pragma unroll
        for (int j=0;j<KS;j++) mx=fmaxf(mx, sc[tid*KS+j]);
        float s=0.f;
        #pragma unroll
        for (int j=0;j<KS;j++){ float e=expf(sc[tid*KS+j]-mx); sc[tid*KS+j]=e; s+=e; }
        float inv=1.0f/s;
        #pragma unroll
        for (int j=0;j<KS;j++) sc[tid*KS+j]*=inv;
    }
    __syncthreads();
    for (int i=tid;i<KS*HDIM;i+=128){
        int s=i/HDIM, c=i%HDIM;
        float o=0.f;
        #pragma unroll
        for (int j=0;j<KS;j++) o = fmaf(sc[s*KS+j], vs[j*HDIM+c], o);
        g_o[(size_t)(b*KS+s)*D + h*HDIM + c] = o;
    }
}

__global__ void copyk(const float* __restrict__ s, float* __restrict__ d, int n){
    int i = blockIdx.x*blockDim.x + threadIdx.x;
    if (i < n) d[i] = s[i];
}

// ---------------- host orchestration ----------------
extern "C" void kernel_launch(void* const* d_in, const int* in_sizes, int n_in,
                              void* d_out, int out_size)
{
    (void)in_sizes; (void)n_in;
    const float* features  = (const float*)d_in[0];
    const float* slots_init= (const float*)d_in[1];
    const float* nf_g=(const float*)d_in[2];  const float* nf_b=(const float*)d_in[3];
    const float* ns_g=(const float*)d_in[4];  const float* ns_b=(const float*)d_in[5];
    const float* Wq =(const float*)d_in[6];   const float* Wk =(const float*)d_in[7];
    const float* Wv =(const float*)d_in[8];
    const float* mg =(const float*)d_in[9];   const float* mb =(const float*)d_in[10];
    const float* mW1=(const float*)d_in[11];  const float* mb1=(const float*)d_in[12];
    const float* mW2=(const float*)d_in[13];  const float* mb2=(const float*)d_in[14];
    const float* b_ln1g=(const float*)d_in[15]; const float* b_ln1b=(const float*)d_in[16];
    const float* b_Wqkv=(const float*)d_in[17]; const float* b_bqkv=(const float*)d_in[18];
    const float* b_Wo=(const float*)d_in[19];   const float* b_bo=(const float*)d_in[20];
    const float* b_ln2g=(const float*)d_in[21]; const float* b_ln2b=(const float*)d_in[22];
    const float* b_W1=(const float*)d_in[23];   const float* b_b1=(const float*)d_in[24];
    const float* b_W2=(const float*)d_in[25];   const float* b_b2=(const float*)d_in[26];

    float *pFn,*pSn,*pQ,*pAttn,*pU,*pUpd,*pX,*pH,*pQkv,*pO,*pResid,*pMlp,*pSlots,*pWqk;
    cudaGetSymbolAddress((void**)&pFn, g_fn);
    cudaGetSymbolAddress((void**)&pSn, g_sn);
    cudaGetSymbolAddress((void**)&pQ, g_q);
    cudaGetSymbolAddress((void**)&pAttn, g_attn);
    cudaGetSymbolAddress((void**)&pU, g_u);
    cudaGetSymbolAddress((void**)&pUpd, g_upd);
    cudaGetSymbolAddress((void**)&pX, g_x);
    cudaGetSymbolAddress((void**)&pH, g_h);
    cudaGetSymbolAddress((void**)&pQkv, g_qkv);
    cudaGetSymbolAddress((void**)&pO, g_o);
    cudaGetSymbolAddress((void**)&pResid, g_resid);
    cudaGetSymbolAddress((void**)&pMlp, g_mlp);
    cudaGetSymbolAddress((void**)&pSlots, g_slots);
    cudaGetSymbolAddress((void**)&pWqk, g_Wqk);

    float* out = (float*)d_out;
    float* mask_dst;
    bool write_slots = true;
    if (out_size == BB*NN*KS){ mask_dst = out; write_slots = false; }
    else if (out_size >= MR*D + BB*NN*KS){ mask_dst = out + MR*D; }
    else { mask_dst = pAttn; }   // slots-only output

    // ---- invariant precompute ----
    copyk<<<(MR*D+255)/256,256>>>(slots_init, pSlots, MR*D);
    ln_kernel<<<FR,256>>>(features, nullptr, nf_g, nf_b, pFn);
    // Wqk = Wq @ Wk^T  (TRB)
    gemmT<64,2,false,false,false,true><<<dim3(D/64, D/64),128>>>(Wq, Wk, nullptr, nullptr, pWqk, D, D, D);

    const int NB = (NN + 31)/32;  // 43
    for (int t=0;t<TT;t++){
        const float* ln1g = b_ln1g + t*D;          const float* ln1b = b_ln1b + t*D;
        const float* Wqkv_t = b_Wqkv + (size_t)t*D*3*D;  const float* bqkv_t = b_bqkv + t*3*D;
        const float* Wo_t = b_Wo + (size_t)t*D*D;  const float* bo_t = b_bo + t*D;
        const float* ln2g = b_ln2g + t*D;          const float* ln2b = b_ln2b + t*D;
        const float* W1_t = b_W1 + (size_t)t*D*4*D; const float* b1_t = b_b1 + t*4*D;
        const float* W2_t = b_W2 + (size_t)t*4*D*D; const float* b2_t = b_b2 + t*D;

        // slot->feature attention (restructured: q = sn @ Wqk, logits = q.fn^T)
        ln_kernel<<<MR,256>>>(pSlots, nullptr, ns_g, ns_b, pSn);
        gemmT<32,4,false,false,false,false><<<dim3(D/64, MR/32),128>>>(pSn, pWqk, nullptr, nullptr, pQ, MR, D, D);
        attn_softmax_kernel<<<dim3(NB,BB),256>>>(pAttn);
        mass_kernel<<<BB,256>>>(pAttn);
        u_part_kernel<<<dim3(3,USPLIT,BB),256>>>(pAttn);
        u_combine_kernel<<<(MR*D+255)/256,256>>>();
        gemmT<32,4,false,false,false,false><<<dim3(D/64, MR/32),128>>>(pU, Wv, nullptr, nullptr, pUpd, MR, D, D);

        // transformer block on sn
        ln_kernel<<<MR,256>>>(pSn, nullptr, ln1g, ln1b, pH);
        gemmT<64,2,true,false,false,false><<<dim3(3*D/64, MR/64),128>>>(pH, Wqkv_t, bqkv_t, nullptr, pQkv, MR, D, 3*D);
        block_attn_kernel<<<BB*HH,128>>>();
        gemmT<32,4,true,false,true,false><<<dim3(D/64, MR/32),128>>>(pO, Wo_t, bo_t, pSn, pX, MR, D, D);
        ln_kernel<<<MR,256>>>(pX, nullptr, ln2g, ln2b, pH);
        gemmT<64,2,true,true,false,false><<<dim3(4*D/64, MR/64),128>>>(pH, W1_t, b1_t, nullptr, pMlp, MR, D, 4*D);
        gemmT<32,4,true,false,true,false><<<dim3(D/64, MR/32),128>>>(pMlp, W2_t, b2_t, pX, pResid, MR, 4*D, D);

        // mixer MLP + slot update
        ln_kernel<<<MR,256>>>(pUpd, pResid, mg, mb, pH);
        gemmT<64,2,true,true,false,false><<<dim3(4*D/64, MR/64),128>>>(pH, mW1, mb1, nullptr, pMlp, MR, D, 4*D);
        gemmT<32,4,true,false,true,false><<<dim3(D/64, MR/32),128>>>(pMlp, mW2, mb2, pSlots, pSlots, MR, 4*D, D);
    }

    // final masks from updated slots
    ln_kernel<<<MR,256>>>(pSlots, nullptr, ns_g, ns_b, pSn);
    gemmT<32,4,false,false,false,false><<<dim3(D/64, MR/32),128>>>(pSn, pWqk, nullptr, nullptr, pQ, MR, D, D);
    attn_softmax_kernel<<<dim3(NB,BB),256>>>(mask_dst);
    if (write_slots)
        copyk<<<(MR*D+255)/256,256>>>(pSlots, out, MR*D);
}

// round 15
// speedup vs baseline: 1.9342x; 1.1827x over previous
#include <cuda_runtime.h>
#include <math.h>
#include <stdint.h>

#define D     768
#define KS    12
#define TT    3
#define BB    32
#define NN    1369
#define HH    8
#define HDIM  96
#define MR    (BB*KS)     // 384 slot rows
#define FR    (BB*NN)     // 43808 feature rows
#define USPLIT 8
#define NBLK  43          // ceil(NN/32)
#define QK_SCALE 0.03608439182435161f   // 768^-0.5
#define HD_SCALE 0.10206207261596577f   // 96^-0.5

// ---------------- scratch (device globals; no allocations) ----------------
__device__ float g_fn[(size_t)FR*D];      // LN(features), invariant
__device__ float g_sn[MR*D];
__device__ float g_q[MR*D];               // sn @ (Wq Wk^T)
__device__ float g_attn[(size_t)BB*NN*KS];
__device__ float g_mass[MR];
__device__ float g_mass_part[(size_t)BB*NBLK*KS];
__device__ float g_u_part[(size_t)USPLIT*MR*D];
__device__ float g_u[MR*D];
__device__ float g_upd[MR*D];
__device__ float g_x[MR*D];
__device__ float g_h[MR*D];
__device__ float g_qkv[MR*3*D];
__device__ float g_o[MR*D];
__device__ float g_resid[MR*D];
__device__ float g_mlp[MR*4*D];
__device__ float g_slots[MR*D];
__device__ float g_Wqk[D*D];              // Wq @ Wk^T

__device__ __forceinline__ float gelu_f(float x){
    return 0.5f*x*(1.0f + erff(x*0.7071067811865476f));
}

__device__ __forceinline__ float tf32r(float x){
    uint32_t u; asm("cvt.rna.tf32.f32 %0, %1;" : "=r"(u) : "f"(x));
    return __uint_as_float(u);
}

__device__ __forceinline__ void mma_tf32(float* d, const uint32_t* a, uint32_t b0, uint32_t b1){
    asm volatile("mma.sync.aligned.m16n8k8.row.col.f32.tf32.tf32.f32 "
        "{%0,%1,%2,%3}, {%4,%5,%6,%7}, {%8,%9}, {%0,%1,%2,%3};"
        : "+f"(d[0]), "+f"(d[1]), "+f"(d[2]), "+f"(d[3])
        : "r"(a[0]), "r"(a[1]), "r"(a[2]), "r"(a[3]), "r"(b0), "r"(b1));
}

// ---------------- layernorm (row = 768, 256 threads/row) ----------------
__global__ void ln_kernel(const float* __restrict__ x, const float* __restrict__ x2,
                          const float* __restrict__ g, const float* __restrict__ b,
                          float* __restrict__ out)
{
    int row = blockIdx.x;
    int tid = threadIdx.x;
    const float* xr = x + (size_t)row*D;
    float v[3]; float s=0.f, sq=0.f;
    #pragma unroll
    for (int i=0;i<3;i++){
        int c = tid + i*256;
        float val = xr[c];
        if (x2) val += x2[(size_t)row*D + c];
        v[i]=val; s+=val; sq = fmaf(val,val,sq);
    }
    __shared__ float r0[8], r1[8];
    #pragma unroll
    for (int o=16;o;o>>=1){ s += __shfl_xor_sync(0xffffffffu,s,o); sq += __shfl_xor_sync(0xffffffffu,sq,o); }
    if ((tid&31)==0){ r0[tid>>5]=s; r1[tid>>5]=sq; }
    __syncthreads();
    if (tid==0){
        float S=0.f,SQ=0.f;
        #pragma unroll
        for (int i=0;i<8;i++){ S+=r0[i]; SQ+=r1[i]; }
        float m = S*(1.0f/D);
        float var = SQ*(1.0f/D) - m*m;
        r0[0]=m; r1[0]=rsqrtf(var + 1e-5f);
    }
    __syncthreads();
    float m=r0[0], inv=r1[0];
    #pragma unroll
    for (int i=0;i<3;i++){
        int c = tid + i*256;
        out[(size_t)row*D + c] = (v[i]-m)*inv*g[c] + b[c];
    }
}

// ---------------- tf32 tensor-core GEMM, 2-stage smem pipeline ----------------
// Block tile: BM x 64, K-chunk 32. 128 threads = 4 warps, layout (BM/32) x WC.
// Warp tile: 32 x (64/WC).  C = epilogue(A[M,K] @ B[K,N]); TRB: B given [N,K].
template<int BM, int WC, bool BIAS, bool GELU_, bool RES, bool TRB>
__global__ void __launch_bounds__(128)
gemmT(const float* __restrict__ A, const float* __restrict__ Bm,
      const float* __restrict__ bias, const float* __restrict__ res,
      float* __restrict__ C, int M, int Kd, int N)
{
    constexpr int SA = BM + 8;      // As stride (words): %32==8 -> conflict-free frag LDS
    constexpr int NT = 8/WC;        // n-tiles (8 cols each) per warp
    constexpr int NA = BM/16;       // A float4 loads per thread
    __shared__ float As[2][32*SA];
    __shared__ float Bs[2][32*72];

    int tid = threadIdx.x;
    int wid = tid>>5, lane = tid&31;
    int grp = lane>>2, tig = lane&3;
    int wrow = wid / WC, wcol = wid % WC;
    int bm = blockIdx.y, bn = blockIdx.x;

    float acc[2][NT][4];
    #pragma unroll
    for (int i=0;i<2;i++)
        #pragma unroll
        for (int j=0;j<NT;j++){ acc[i][j][0]=0.f; acc[i][j][1]=0.f; acc[i][j][2]=0.f; acc[i][j][3]=0.f; }

    // global loaders
    int arow = tid>>3, aq = tid&7;
    const float* Ap = A + (size_t)(bm*BM + arow)*Kd + aq*4;
    int bkrow = tid>>4, bq = tid&15;
    int brow = tid>>3, bq2 = tid&7;
    const float* Bp;
    if (TRB) Bp = Bm + (size_t)(bn*64 + brow)*Kd + bq2*4;
    else     Bp = Bm + (size_t)bkrow*N + bn*64 + bq*4;

    float4 pa[NA], pb[4];

    auto LDG_ALL = [&](){
        #pragma unroll
        for (int i=0;i<NA;i++) pa[i] = *(const float4*)(Ap + (size_t)(16*i)*Kd);
        if (TRB){
            #pragma unroll
            for (int i=0;i<4;i++) pb[i] = *(const float4*)(Bp + (size_t)(16*i)*Kd);
            Bp += 32;
        } else {
            #pragma unroll
            for (int i=0;i<4;i++) pb[i] = *(const float4*)(Bp + (size_t)(8*i)*N);
            Bp += (size_t)32*N;
        }
        Ap += 32;
    };

    auto STS_ALL = [&](int buf){
        #pragma unroll
        for (int i=0;i<NA;i++){
            int row = arow + 16*i;
            float v[4] = {pa[i].x, pa[i].y, pa[i].z, pa[i].w};
            #pragma unroll
            for (int j=0;j<4;j++){
                int k = aq*4 + j;
                As[buf][k*SA + (row ^ ((((k>>2)&7))<<2))] = tf32r(v[j]);
            }
        }
        if (TRB){
            #pragma unroll
            for (int i=0;i<4;i++){
                int row = brow + 16*i;   // n index
                float v[4] = {pb[i].x, pb[i].y, pb[i].z, pb[i].w};
                #pragma unroll
                for (int j=0;j<4;j++){
                    int k = bq2*4 + j;
                    Bs[buf][k*72 + (row ^ ((((k>>2)&7))<<2))] = tf32r(v[j]);
                }
            }
        } else {
            #pragma unroll
            for (int i=0;i<4;i++){
                int kr = bkrow + 8*i;
                float4 cv;
                cv.x = tf32r(pb[i].x); cv.y = tf32r(pb[i].y);
                cv.z = tf32r(pb[i].z); cv.w = tf32r(pb[i].w);
                int cb = (bq*4) ^ ((((kr>>2)&7))<<2);
                *(float4*)&Bs[buf][kr*72 + cb] = cv;
            }
        }
    };

    auto COMPUTE = [&](int buf){
        #pragma unroll
        for (int ks=0; ks<4; ks++){
            int k0 = ks*8;
            int kA = k0 + tig, kB = k0 + tig + 4;
            int c1 = (((kA>>2)&7))<<2;   // constant per instruction (tig<4)
            int c2 = (((kB>>2)&7))<<2;
            uint32_t af[2][4];
            #pragma unroll
            for (int mt=0;mt<2;mt++){
                int m0 = wrow*32 + mt*16 + grp;
                af[mt][0] = __float_as_uint(As[buf][kA*SA + ( m0      ^ c1)]);
                af[mt][1] = __float_as_uint(As[buf][kA*SA + ((m0+8)   ^ c1)]);
                af[mt][2] = __float_as_uint(As[buf][kB*SA + ( m0      ^ c2)]);
                af[mt][3] = __float_as_uint(As[buf][kB*SA + ((m0+8)   ^ c2)]);
            }
            #pragma unroll
            for (int nt=0;nt<NT;nt++){
                int n0 = wcol*(NT*8) + nt*8 + grp;
                uint32_t b0 = __float_as_uint(Bs[buf][kA*72 + (n0 ^ c1)]);
                uint32_t b1 = __float_as_uint(Bs[buf][kB*72 + (n0 ^ c2)]);
                #pragma unroll
                for (int mt=0;mt<2;mt++)
                    mma_tf32(acc[mt][nt], af[mt], b0, b1);
            }
        }
    };

    int nch = Kd >> 5;
    // prologue: chunk0 -> buf0; prefetch chunk1
    LDG_ALL();
    STS_ALL(0);
    __syncthreads();
    if (nch > 1) LDG_ALL();

    int p = 0;
    for (int c=0; c<nch; c++){
        if (c+1 < nch) STS_ALL(1-p);
        COMPUTE(p);
        __syncthreads();
        if (c+2 < nch) LDG_ALL();
        p ^= 1;
    }

    // ---- epilogue ----
    #pragma unroll
    for (int mt=0;mt<2;mt++){
        #pragma unroll
        for (int nt=0;nt<NT;nt++){
            int row0 = bm*BM + wrow*32 + mt*16 + grp;
            int col0 = bn*64 + wcol*(NT*8) + nt*8 + tig*2;
            #pragma unroll
            for (int h=0;h<2;h++){
                int r = row0 + 8*h;
                float vx = acc[mt][nt][2*h];
                float vy = acc[mt][nt][2*h+1];
                if (BIAS){ vx += bias[col0]; vy += bias[col0+1]; }
                if (GELU_){ vx = gelu_f(vx); vy = gelu_f(vy); }
                if (RES){ vx += res[(size_t)r*N + col0]; vy += res[(size_t)r*N + col0+1]; }
                float2 v2; v2.x = vx; v2.y = vy;
                *(float2*)&C[(size_t)r*N + col0] = v2;
            }
        }
    }
}

// ---------------- fused logits + softmax + per-block mass partials ----------------
__global__ void attn_softmax_kernel(float* __restrict__ attn_out)
{
    __shared__ __align__(16) float qs[KS*D];   // 36 KB
    __shared__ float ms[8][KS];
    int b = blockIdx.y;
    int n0 = blockIdx.x * 32;
    int tid = threadIdx.x;
    const float* qb = g_q + (size_t)b*KS*D;
    for (int i=tid; i<KS*D/4; i+=256)
        ((float4*)qs)[i] = ((const float4*)qb)[i];
    __syncthreads();
    int warp = tid>>5, lane = tid&31;
    float msum = 0.f;   // lane<KS: running mass for slot `lane`
    for (int nw=0; nw<4; nw++){
        int n = n0 + warp*4 + nw;
        if (n >= NN) continue;
        const float* f = g_fn + ((size_t)b*NN + n)*D;
        float acc[KS];
        #pragma unroll
        for (int k=0;k<KS;k++) acc[k]=0.f;
        for (int d0=0; d0<D; d0+=32){
            float fv = f[d0+lane];
            #pragma unroll
            for (int k=0;k<KS;k++) acc[k] = fmaf(fv, qs[k*D + d0 + lane], acc[k]);
        }
        #pragma unroll
        for (int k=0;k<KS;k++){
            #pragma unroll
            for (int o=16;o;o>>=1) acc[k] += __shfl_xor_sync(0xffffffffu, acc[k], o);
        }
        float mx = -1e30f;
        #pragma unroll
        for (int k=0;k<KS;k++){ acc[k]*=QK_SCALE; mx = fmaxf(mx, acc[k]); }
        float s=0.f;
        #pragma unroll
        for (int k=0;k<KS;k++){ acc[k]=expf(acc[k]-mx); s+=acc[k]; }
        float inv = 1.0f/s;
        if (lane < KS){
            float val=0.f;
            #pragma unroll
            for (int k=0;k<KS;k++) if (lane==k) val = acc[k];
            val *= inv;
            attn_out[((size_t)b*NN + n)*KS + lane] = val;
            msum += val;
        }
    }
    if (lane < KS) ms[warp][lane] = msum;
    __syncthreads();
    if (tid < KS){
        float s = 0.f;
        #pragma unroll
        for (int w=0;w<8;w++) s += ms[w][tid];
        g_mass_part[((size_t)b*NBLK + blockIdx.x)*KS + tid] = s;
    }
}

// ---------------- mass[b,k] = fixed-order sum of per-block partials ----------------
__global__ void mass_combine_kernel(){
    int i = threadIdx.x;           // 384 threads, 1 block
    if (i < MR){
        int b = i / KS, k = i % KS;
        float s = 0.f;
        #pragma unroll 1
        for (int j=0;j<NBLK;j++) s += g_mass_part[((size_t)b*NBLK + j)*KS + k];
        g_mass[i] = s;
    }
}

// ---------------- u_part[s,b,k,d] = sum_{n in split s} attn[b,n,k]*fn[b,n,d] ----
__global__ void u_part_kernel(const float* __restrict__ attn)
{
    __shared__ float as[64*KS];
    int b = blockIdx.z;
    int sp = blockIdx.y;
    int d = blockIdx.x*256 + threadIdx.x;
    const int nchunk = (NN + USPLIT - 1)/USPLIT;   // 172
    int ns = sp * nchunk;
    int ne = min(ns + nchunk, NN);
    float acc[KS];
    #pragma unroll
    for (int k=0;k<KS;k++) acc[k]=0.f;
    for (int nb=ns; nb<ne; nb+=64){
        int cnt = min(64, ne-nb);
        __syncthreads();
        for (int i=threadIdx.x; i<cnt*KS; i+=256)
            as[i] = attn[((size_t)b*NN + nb)*KS + i];
        __syncthreads();
        for (int j=0;j<cnt;j++){
            float fv = g_fn[((size_t)b*NN + nb + j)*D + d];
            #pragma unroll
            for (int k=0;k<KS;k++) acc[k] = fmaf(fv, as[j*KS+k], acc[k]);
        }
    }
    #pragma unroll
    for (int k=0;k<KS;k++)
        g_u_part[((size_t)sp*MR + b*KS + k)*D + d] = acc[k];
}

// ---------------- u = (sum of partials) / max(mass, eps), fixed order --------
__global__ void u_combine_kernel(){
    int i = blockIdx.x*256 + threadIdx.x;
    if (i >= MR*D) return;
    float s = 0.f;
    #pragma unroll
    for (int p=0;p<USPLIT;p++) s += g_u_part[(size_t)p*MR*D + i];
    g_u[i] = s / fmaxf(g_mass[i/D], 1e-8f);
}

// ---------------- tiny 12-token 8-head transformer attention ----------------
__global__ void block_attn_kernel()
{
    int b = blockIdx.x / HH, h = blockIdx.x % HH;
    __shared__ float qs[KS*HDIM], ks2[KS*HDIM], vs[KS*HDIM], sc[KS*KS];
    int tid = threadIdx.x;  // 128
    for (int i=tid;i<KS*HDIM;i+=128){
        int s=i/HDIM, c=i%HDIM;
        const float* r = g_qkv + (size_t)(b*KS+s)*(3*D) + h*HDIM + c;
        qs[i]=r[0]; ks2[i]=r[D]; vs[i]=r[2*D];
    }
    __syncthreads();
    for (int t=tid;t<KS*KS;t+=128){
        int i=t/KS, j=t%KS;
        float sum=0.f;
        #pragma unroll
        for (int c=0;c<HDIM;c++) sum = fmaf(qs[i*HDIM+c], ks2[j*HDIM+c], sum);
        sc[t] = sum * HD_SCALE;
    }
    __syncthreads();
    if (tid < KS){
        float mx=-1e30f;
        #pragma unroll
        for (int j=0;j<KS;j++) mx=fmaxf(mx, sc[tid*KS+j]);
        float s=0.f;
        #pragma unroll
        for (int j=0;j<KS;j++){ float e=expf(sc[tid*KS+j]-mx); sc[tid*KS+j]=e; s+=e; }
        float inv=1.0f/s;
        #pragma unroll
        for (int j=0;j<KS;j++) sc[tid*KS+j]*=inv;
    }
    __syncthreads();
    for (int i=tid;i<KS*HDIM;i+=128){
        int s=i/HDIM, c=i%HDIM;
        float o=0.f;
        #pragma unroll
        for (int j=0;j<KS;j++) o = fmaf(sc[s*KS+j], vs[j*HDIM+c], o);
        g_o[(size_t)(b*KS+s)*D + h*HDIM + c] = o;
    }
}

__global__ void copyk(const float* __restrict__ s, float* __restrict__ d, int n){
    int i = blockIdx.x*blockDim.x + threadIdx.x;
    if (i < n) d[i] = s[i];
}

// ---------------- host orchestration ----------------
extern "C" void kernel_launch(void* const* d_in, const int* in_sizes, int n_in,
                              void* d_out, int out_size)
{
    (void)in_sizes; (void)n_in;
    const float* features  = (const float*)d_in[0];
    const float* slots_init= (const float*)d_in[1];
    const float* nf_g=(const float*)d_in[2];  const float* nf_b=(const float*)d_in[3];
    const float* ns_g=(const float*)d_in[4];  const float* ns_b=(const float*)d_in[5];
    const float* Wq =(const float*)d_in[6];   const float* Wk =(const float*)d_in[7];
    const float* Wv =(const float*)d_in[8];
    const float* mg =(const float*)d_in[9];   const float* mb =(const float*)d_in[10];
    const float* mW1=(const float*)d_in[11];  const float* mb1=(const float*)d_in[12];
    const float* mW2=(const float*)d_in[13];  const float* mb2=(const float*)d_in[14];
    const float* b_ln1g=(const float*)d_in[15]; const float* b_ln1b=(const float*)d_in[16];
    const float* b_Wqkv=(const float*)d_in[17]; const float* b_bqkv=(const float*)d_in[18];
    const float* b_Wo=(const float*)d_in[19];   const float* b_bo=(const float*)d_in[20];
    const float* b_ln2g=(const float*)d_in[21]; const float* b_ln2b=(const float*)d_in[22];
    const float* b_W1=(const float*)d_in[23];   const float* b_b1=(const float*)d_in[24];
    const float* b_W2=(const float*)d_in[25];   const float* b_b2=(const float*)d_in[26];

    float *pFn,*pSn,*pQ,*pAttn,*pU,*pUpd,*pX,*pH,*pQkv,*pO,*pResid,*pMlp,*pSlots,*pWqk;
    cudaGetSymbolAddress((void**)&pFn, g_fn);
    cudaGetSymbolAddress((void**)&pSn, g_sn);
    cudaGetSymbolAddress((void**)&pQ, g_q);
    cudaGetSymbolAddress((void**)&pAttn, g_attn);
    cudaGetSymbolAddress((void**)&pU, g_u);
    cudaGetSymbolAddress((void**)&pUpd, g_upd);
    cudaGetSymbolAddress((void**)&pX, g_x);
    cudaGetSymbolAddress((void**)&pH, g_h);
    cudaGetSymbolAddress((void**)&pQkv, g_qkv);
    cudaGetSymbolAddress((void**)&pO, g_o);
    cudaGetSymbolAddress((void**)&pResid, g_resid);
    cudaGetSymbolAddress((void**)&pMlp, g_mlp);
    cudaGetSymbolAddress((void**)&pSlots, g_slots);
    cudaGetSymbolAddress((void**)&pWqk, g_Wqk);

    // side stream + events for the fork/join overlap (host objects; created once)
    static cudaStream_t sB = nullptr;
    static cudaEvent_t evF = nullptr, evB = nullptr;
    if (!sB){
        cudaStreamCreateWithFlags(&sB, cudaStreamNonBlocking);
        cudaEventCreateWithFlags(&evF, cudaEventDisableTiming);
        cudaEventCreateWithFlags(&evB, cudaEventDisableTiming);
    }

    float* out = (float*)d_out;
    float* mask_dst;
    bool write_slots = true;
    if (out_size == BB*NN*KS){ mask_dst = out; write_slots = false; }
    else if (out_size >= MR*D + BB*NN*KS){ mask_dst = out + MR*D; }
    else { mask_dst = pAttn; }   // slots-only output

    // ---- invariant precompute ----
    copyk<<<(MR*D+255)/256,256>>>(slots_init, pSlots, MR*D);
    ln_kernel<<<FR,256>>>(features, nullptr, nf_g, nf_b, pFn);
    // Wqk = Wq @ Wk^T  (TRB)
    gemmT<64,2,false,false,false,true><<<dim3(D/64, D/64),128>>>(Wq, Wk, nullptr, nullptr, pWqk, D, D, D);

    for (int t=0;t<TT;t++){
        const float* ln1g = b_ln1g + t*D;          const float* ln1b = b_ln1b + t*D;
        const float* Wqkv_t = b_Wqkv + (size_t)t*D*3*D;  const float* bqkv_t = b_bqkv + t*3*D;
        const float* Wo_t = b_Wo + (size_t)t*D*D;  const float* bo_t = b_bo + t*D;
        const float* ln2g = b_ln2g + t*D;          const float* ln2b = b_ln2b + t*D;
        const float* W1_t = b_W1 + (size_t)t*D*4*D; const float* b1_t = b_b1 + t*4*D;
        const float* W2_t = b_W2 + (size_t)t*4*D*D; const float* b2_t = b_b2 + t*D;

        // sn = LN(slots)  — both chains depend on this
        ln_kernel<<<MR,256>>>(pSlots, nullptr, ns_g, ns_b, pSn);

        // fork: chain B (transformer block) on side stream
        cudaEventRecord(evF, 0);
        cudaStreamWaitEvent(sB, evF, 0);
        ln_kernel<<<MR,256,0,sB>>>(pSn, nullptr, ln1g, ln1b, pH);
        gemmT<64,2,true,false,false,false><<<dim3(3*D/64, MR/64),128,0,sB>>>(pH, Wqkv_t, bqkv_t, nullptr, pQkv, MR, D, 3*D);
        block_attn_kernel<<<BB*HH,128,0,sB>>>();
        gemmT<32,4,true,false,true,false><<<dim3(D/64, MR/32),128,0,sB>>>(pO, Wo_t, bo_t, pSn, pX, MR, D, D);
        ln_kernel<<<MR,256,0,sB>>>(pX, nullptr, ln2g, ln2b, pH);
        gemmT<64,2,true,true,false,false><<<dim3(4*D/64, MR/64),128,0,sB>>>(pH, W1_t, b1_t, nullptr, pMlp, MR, D, 4*D);
        gemmT<32,4,true,false,true,false><<<dim3(D/64, MR/32),128,0,sB>>>(pMlp, W2_t, b2_t, pX, pResid, MR, 4*D, D);
        cudaEventRecord(evB, sB);

        // chain A (slot->feature attention) on main stream
        gemmT<32,4,false,false,false,false><<<dim3(D/64, MR/32),128>>>(pSn, pWqk, nullptr, nullptr, pQ, MR, D, D);
        attn_softmax_kernel<<<dim3(NBLK,BB),256>>>(pAttn);
        mass_combine_kernel<<<1,MR>>>();
        u_part_kernel<<<dim3(3,USPLIT,BB),256>>>(pAttn);
        u_combine_kernel<<<(MR*D+255)/256,256>>>();
        gemmT<32,4,false,false,false,false><<<dim3(D/64, MR/32),128>>>(pU, Wv, nullptr, nullptr, pUpd, MR, D, D);

        // join, then mixer MLP + slot update
        cudaStreamWaitEvent(0, evB, 0);
        ln_kernel<<<MR,256>>>(pUpd, pResid, mg, mb, pH);
        gemmT<64,2,true,true,false,false><<<dim3(4*D/64, MR/64),128>>>(pH, mW1, mb1, nullptr, pMlp, MR, D, 4*D);
        gemmT<32,4,true,false,true,false><<<dim3(D/64, MR/32),128>>>(pMlp, mW2, mb2, pSlots, pSlots, MR, 4*D, D);
    }

    // final masks from updated slots
    ln_kernel<<<MR,256>>>(pSlots, nullptr, ns_g, ns_b, pSn);
    gemmT<32,4,false,false,false,false><<<dim3(D/64, MR/32),128>>>(pSn, pWqk, nullptr, nullptr, pQ, MR, D, D);
    attn_softmax_kernel<<<dim3(NBLK,BB),256>>>(mask_dst);
    if (write_slots)
        copyk<<<(MR*D+255)/256,256>>>(pSlots, out, MR*D);
}